// round 15
// baseline (speedup 1.0000x reference)
#include <cuda_runtime.h>
#include <cuda_fp16.h>
#include <cstdint>

// ---------------------------------------------------------------------------
// KAN-Mixer fused kernel (round 9): fp16 mma.sync m16n8k16, fp32 accumulate,
// cp.async double-buffered weights, h fp16 in smem. Round-9 delta: MTILE 32
// (grid 1536) to cut per-SM CTA quantization from ~16% to ~6%.
// ---------------------------------------------------------------------------

#define PP   196
#define CC   768
#define HSZ  384

#define NT1  48            // n8 tiles layer1
#define NC1  56            // chunks of 32 k
#define NT2  25            // n8 tiles layer2 (200 = 196 padded to 8)
#define NC2  108

#define MTILE 32
#define NTH  256
#define L2E  1.4426950408889634f

#define W1ELEMS (112u * 48u * 64u)     // 344064 uints
#define W2ELEMS (216u * 25u * 64u)     // 345600 uints
#define L2CHUNK (25u * 64u * 2u)       // 3200 uints per 32-k chunk

// fragment-ordered packed fp16 weights (uint = half2):
// index = (ks16*NT + nt)*64 + lane*2 + r ; half2 = {W[n][k], W[n][k+1]},
// n = nt*8 + lane/4, k = ks16*16 + r*8 + (lane%4)*2
__device__ unsigned g_W1[W1ELEMS];   // 1.31 MB
__device__ unsigned g_W2[W2ELEMS];   // 1.32 MB

// ----------------------------- helpers --------------------------------------
static __device__ __forceinline__ float ex2f(float z) {
    float r; asm("ex2.approx.ftz.f32 %0, %1;" : "=f"(r) : "f"(z)); return r;
}
static __device__ __forceinline__ float rcpf(float z) {
    float r; asm("rcp.approx.ftz.f32 %0, %1;" : "=f"(r) : "f"(z)); return r;
}
static __device__ __forceinline__ float silu_feat(float v) {
    float z = fminf(fmaxf(-v * L2E, -126.0f), 126.0f);
    return v * rcpf(1.0f + ex2f(z));
}
static __device__ __forceinline__ unsigned h2pack(float a, float b) {
    __half2 h = __floats2half2_rn(a, b);
    return *reinterpret_cast<unsigned*>(&h);
}
static __device__ __forceinline__ void mma16(float* d, const uint4& A, const uint2& B) {
    asm volatile(
        "mma.sync.aligned.m16n8k16.row.col.f32.f16.f16.f32 "
        "{%0,%1,%2,%3}, {%4,%5,%6,%7}, {%8,%9}, {%0,%1,%2,%3};"
        : "+f"(d[0]), "+f"(d[1]), "+f"(d[2]), "+f"(d[3])
        : "r"(A.x), "r"(A.y), "r"(A.z), "r"(A.w), "r"(B.x), "r"(B.y));
}
static __device__ __forceinline__ void cpasync16(void* dst, const void* src) {
    unsigned s = (unsigned)__cvta_generic_to_shared(dst);
    asm volatile("cp.async.cg.shared.global [%0], [%1], 16;" :: "r"(s), "l"(src));
}
static __device__ __forceinline__ void cp_commit() {
    asm volatile("cp.async.commit_group;" ::: "memory");
}
static __device__ __forceinline__ void cp_wait0() {
    asm volatile("cp.async.wait_group 0;" ::: "memory");
}

// ------------------------- fused weight prep --------------------------------
__global__ void prep(const float* __restrict__ sw1, const float* __restrict__ bw1,
                     const float* __restrict__ sw2, const float* __restrict__ bw2) {
    unsigned gi = blockIdx.x * blockDim.x + threadIdx.x;
    if (gi < W1ELEMS) {
        unsigned idx = gi;
        unsigned r = idx & 1, lane = (idx >> 1) & 31;
        unsigned nt = (idx >> 6) % 48, ks = (idx >> 6) / 48;
        unsigned n = nt * 8 + (lane >> 2);
        unsigned k = ks * 16 + r * 8 + (lane & 3) * 2;
        float v0 = 0.0f, v1 = 0.0f;
        if (k < 1568)       v0 = sw1[n * 1568 + k];
        else if (k < 1764)  v0 = bw1[n * 196 + (k - 1568)];
        unsigned k1 = k + 1;
        if (k1 < 1568)      v1 = sw1[n * 1568 + k1];
        else if (k1 < 1764) v1 = bw1[n * 196 + (k1 - 1568)];
        g_W1[idx] = h2pack(v0, v1);
    } else if (gi < W1ELEMS + W2ELEMS) {
        unsigned idx = gi - W1ELEMS;
        unsigned r = idx & 1, lane = (idx >> 1) & 31;
        unsigned nt = (idx >> 6) % 25, ks = (idx >> 6) / 25;
        unsigned n = nt * 8 + (lane >> 2);
        unsigned k = ks * 16 + r * 8 + (lane & 3) * 2;
        float v0 = 0.0f, v1 = 0.0f;
        if (n < PP) {
            if (k < 3072)       v0 = sw2[n * 3072 + k];
            else                v0 = bw2[n * 384 + (k - 3072)];
            unsigned k1 = k + 1;
            if (k1 < 3072)      v1 = sw2[n * 3072 + k1];
            else                v1 = bw2[n * 384 + (k1 - 3072)];
        }
        g_W2[idx] = h2pack(v0, v1);
    }
}

// ------------------------------ main kernel ---------------------------------
// smem (float units):
//   [0,384)       b1s
//   [384,608)     b2s
//   [640,6912)    region0: xs fp32 [196][32] (L1) / hs fp16 [32][392] (L2)
//   [6912,7424)   As0  (512 f = 128 uint4 fragments)
//   [7424,7936)   As1
//   [7936,14080)  Bs0  (6144 uints for L1 chunk; L2 chunk uses 3200)
//   [14080,20224) Bs1
#define SM_B1   0
#define SM_B2   384
#define SM_R0   640
#define SM_A0   6912
#define SM_A1   7424
#define SM_BS0  7936
#define SM_BS1  14080
#define SM_TOTF 20224
#define HST     392        // h stride in halfs

__global__ void __launch_bounds__(NTH, 2)
kan_main(const float* __restrict__ x, const float* __restrict__ b1,
         const float* __restrict__ b2, float* __restrict__ out) {
    extern __shared__ float smem[];
    float*  b1s = smem + SM_B1;
    float*  b2s = smem + SM_B2;
    float*  xs  = smem + SM_R0;                              // fp32 [196][32]
    __half* hs  = reinterpret_cast<__half*>(smem + SM_R0);   // fp16 [32][392]
    unsigned* Bsu[2] = { reinterpret_cast<unsigned*>(smem + SM_BS0),
                         reinterpret_cast<unsigned*>(smem + SM_BS1) };
    uint4* As4[2] = { reinterpret_cast<uint4*>(smem + SM_A0),
                      reinterpret_cast<uint4*>(smem + SM_A1) };
    uint2* As2u[2] = { reinterpret_cast<uint2*>(smem + SM_A0),
                       reinterpret_cast<uint2*>(smem + SM_A1) };

    const int tid = threadIdx.x;
    const int w = tid >> 5, lane = tid & 31;
    const int mw = w & 1;           // m16 tile (rows [mw*16, mw*16+16))
    const int nG = w >> 1;          // col group 0..3
    const int g = lane >> 2, c4 = lane & 3;
    // L2 n-tile assignment: 25 tiles split 7/6/6/6 over nG
    const int nt2_base = (nG == 0) ? 0 : (1 + 6 * nG);   // 0,7,13,19
    const int nt2_cnt  = (nG == 0) ? 7 : 6;

    // feature-gen decomposition: thread -> uint2 (half a fragment)
    const int fh  = tid & 1;            // half: 0 -> k-lo pair, 1 -> k-hi pair
    const int fno = tid >> 1;           // fragment index 0..127
    const int lf  = fno & 31, ksf = (fno >> 5) & 1, mtf = fno >> 6;
    const int gf  = lf >> 2, c4f = lf & 3;
    const int R0  = mtf * 16 + gf;      // row (R0 and R0+8)
    const float C0f = 3.5f - 2.0f * (float)c4f;   // q0 = 2*c4f

    const int m0 = blockIdx.x * MTILE;
    const int b  = m0 / CC;
    const int c0 = m0 % CC;

    // paired RBF features for (q0, q0+1) from one value: 2 ex2, ~5 flops
    auto bpairf = [&](float v) -> unsigned {
        float d  = fmaf(v, 3.5f, C0f);
        float z0 = d * (d * (-L2E));                       // -(d^2) log2e
        float z1 = fmaf(d, 2.0f * L2E, z0) - L2E;          // -((d-1)^2) log2e
        return h2pack(ex2f(z0), ex2f(z1));
    };

    // ---- prefetch L1 chunk 0 weights ----
#pragma unroll
    for (int i = 0; i < 6; ++i) {
        int v = tid + i * NTH;
        cpasync16(Bsu[0] + v * 4, g_W1 + (size_t)v * 4);
    }
    cp_commit();

    // ---- load x slab + biases ----
    {
        const float4* xg = reinterpret_cast<const float4*>(x + (size_t)b * PP * CC + c0);
        float4* xs4 = reinterpret_cast<float4*>(xs);
        for (int i = tid; i < PP * 8; i += NTH) {
            int p = i >> 3, r4 = i & 7;
            xs4[p * 8 + r4] = xg[p * (CC / 4) + r4];
        }
        for (int i = tid; i < HSZ; i += NTH) b1s[i] = b1[i];
        if (tid < 200) b2s[tid] = (tid < PP) ? b2[tid] : 0.0f;
    }
    __syncthreads();

    // ============================ layer 1 ============================
    {
        float acc[12][4] = {};

        for (int kc = 0; kc < NC1; ++kc) {
            const int bi = kc & 1;

            // generate A half-fragment (uint2 = 4 fp16) per thread
            {
                const int kb = kc * 32 + ksf * 16 + c4f * 2 + fh * 8;
                uint2 aw;
                if (kc < 49) {     // pure basis region: (kb,kb+1) share p, q=2c4f
                    const int p0 = kb >> 3;
                    aw.x = bpairf(xs[p0 * 32 + R0]);
                    aw.y = bpairf(xs[p0 * 32 + R0 + 8]);
                } else {           // silu / pad region, each k -> its own p
                    const int pa = kb - 1568, pb = pa + 1;
                    float fa0 = (pa < PP) ? silu_feat(xs[pa * 32 + R0]) : 0.0f;
                    float fb0 = (pb < PP) ? silu_feat(xs[pb * 32 + R0]) : 0.0f;
                    float fa1 = (pa < PP) ? silu_feat(xs[pa * 32 + R0 + 8]) : 0.0f;
                    float fb1 = (pb < PP) ? silu_feat(xs[pb * 32 + R0 + 8]) : 0.0f;
                    aw.x = h2pack(fa0, fb0);
                    aw.y = h2pack(fa1, fb1);
                }
                As2u[bi][tid] = aw;
            }
            cp_wait0();
            __syncthreads();

            // prefetch next weight chunk
            if (kc + 1 < NC1) {
                const unsigned* src = g_W1 + (size_t)(kc + 1) * 6144;
                unsigned* dst = Bsu[bi ^ 1];
#pragma unroll
                for (int i = 0; i < 6; ++i) {
                    int v = tid + i * NTH;
                    cpasync16(dst + v * 4, src + (size_t)v * 4);
                }
                cp_commit();
            } else {
                // last L1 chunk (kc=55, odd) -> prefetch L2 chunk 0 into Bs0
                unsigned* dst = Bsu[0];
#pragma unroll
                for (int i = 0; i < 3; ++i) {
                    int v = tid + i * NTH;
                    cpasync16(dst + v * 4, g_W2 + (size_t)v * 4);
                }
                if (tid < 32) cpasync16(dst + (768 + tid) * 4, g_W2 + (size_t)(768 + tid) * 4);
                cp_commit();
            }

            // MMA
            const uint2* Bs2 = reinterpret_cast<const uint2*>(Bsu[bi]);
#pragma unroll
            for (int ks = 0; ks < 2; ++ks) {
                uint4 Af = As4[bi][(mw * 2 + ks) * 32 + lane];
#pragma unroll
                for (int nti = 0; nti < 12; ++nti) {
                    int nt = nG * 12 + nti;
                    uint2 Bf = Bs2[(ks * NT1 + nt) * 32 + lane];
                    mma16(acc[nti], Af, Bf);
                }
            }
        }

        __syncthreads();   // all warps done reading xs before hs overwrite

        // ---- h epilogue: hs[row][col] = fp16(acc + b1[col]) ----
#pragma unroll
        for (int nti = 0; nti < 12; ++nti)
#pragma unroll
            for (int ci = 0; ci < 4; ++ci) {
                int row = mw * 16 + g + 8 * (ci >> 1);
                int col = nG * 96 + nti * 8 + 2 * c4 + (ci & 1);
                hs[row * HST + col] = __float2half(acc[nti][ci] + b1s[col]);
            }
    }
    __syncthreads();       // hs visible to all

    // ============================ layer 2 ============================
    {
        float acc[7][4] = {};

        for (int kc = 0; kc < NC2; ++kc) {
            const int bi = kc & 1;

            {
                const int kb = kc * 32 + ksf * 16 + c4f * 2 + fh * 8;
                uint2 aw;
                if (kc < 96) {     // basis over h
                    const int j0 = kb >> 3;
                    aw.x = bpairf(__half2float(hs[R0 * HST + j0]));
                    aw.y = bpairf(__half2float(hs[(R0 + 8) * HST + j0]));
                } else {           // silu over h, k in [3072, 3456)
                    const int ja = kb - 3072;
                    aw.x = h2pack(silu_feat(__half2float(hs[R0 * HST + ja])),
                                  silu_feat(__half2float(hs[R0 * HST + ja + 1])));
                    aw.y = h2pack(silu_feat(__half2float(hs[(R0 + 8) * HST + ja])),
                                  silu_feat(__half2float(hs[(R0 + 8) * HST + ja + 1])));
                }
                As2u[bi][tid] = aw;
            }
            cp_wait0();
            __syncthreads();

            if (kc + 1 < NC2) {
                const unsigned* src = g_W2 + (size_t)(kc + 1) * L2CHUNK;
                unsigned* dst = Bsu[bi ^ 1];
#pragma unroll
                for (int i = 0; i < 3; ++i) {
                    int v = tid + i * NTH;
                    cpasync16(dst + v * 4, src + (size_t)v * 4);
                }
                if (tid < 32) cpasync16(dst + (768 + tid) * 4, src + (size_t)(768 + tid) * 4);
                cp_commit();
            }

            const uint2* Bs2 = reinterpret_cast<const uint2*>(Bsu[bi]);
#pragma unroll
            for (int ks = 0; ks < 2; ++ks) {
                uint4 Af = As4[bi][(mw * 2 + ks) * 32 + lane];
#pragma unroll
                for (int nti = 0; nti < 7; ++nti) {
                    if (nti < nt2_cnt) {
                        int nt = nt2_base + nti;
                        uint2 Bf = Bs2[(ks * NT2 + nt) * 32 + lane];
                        mma16(acc[nti], Af, Bf);
                    }
                }
            }
        }

        // ---- epilogue: out = acc + b2[p] + x (x re-read from gmem) ----
#pragma unroll
        for (int nti = 0; nti < 7; ++nti) {
            if (nti < nt2_cnt) {
#pragma unroll
                for (int ci = 0; ci < 4; ++ci) {
                    int row = mw * 16 + g + 8 * (ci >> 1);
                    int p   = (nt2_base + nti) * 8 + 2 * c4 + (ci & 1);
                    if (p < PP) {
                        size_t ga = ((size_t)b * PP + p) * CC + c0 + row;
                        out[ga] = acc[nti][ci] + b2s[p] + x[ga];
                    }
                }
            }
        }
    }
}

// ------------------------------ launcher ------------------------------------
extern "C" void kernel_launch(void* const* d_in, const int* in_sizes, int n_in,
                              void* d_out, int out_size) {
    (void)in_sizes; (void)n_in; (void)out_size;
    const float* x  = (const float*)d_in[0];
    const float* s1 = (const float*)d_in[1];
    const float* w1 = (const float*)d_in[2];
    const float* b1 = (const float*)d_in[3];
    const float* s2 = (const float*)d_in[4];
    const float* w2 = (const float*)d_in[5];
    const float* b2 = (const float*)d_in[6];
    float* out = (float*)d_out;

    prep<<<(W1ELEMS + W2ELEMS + 255) / 256, 256>>>(s1, w1, s2, w2);

    const int smemBytes = SM_TOTF * 4;   // 80,896 B -> 2 CTAs/SM
    cudaFuncSetAttribute(kan_main, cudaFuncAttributeMaxDynamicSharedMemorySize, smemBytes);
    kan_main<<<(64 * CC) / MTILE, NTH, smemBytes>>>(x, b1, b2, out);
}

// round 16
// speedup vs baseline: 1.3686x; 1.3686x over previous
#include <cuda_runtime.h>
#include <cuda_fp16.h>
#include <cstdint>

// ---------------------------------------------------------------------------
// KAN-Mixer fused kernel (round 10): fp16 mma.sync m16n8k16.
// Spline region (88% of HMMAs, tiny per-term magnitudes) accumulates in FP16
// (testing the 2x f16-acc rate hypothesis); base region (large silu*w terms)
// stays on FP32-acc mma. Streamed merge between regions. MTILE=64, 2 CTAs/SM,
// cp.async double-buffered weights, h fp16 in smem.
// ---------------------------------------------------------------------------

#define PP   196
#define CC   768
#define HSZ  384

#define NT1  48            // n8 tiles layer1
#define NC1  56            // chunks of 32 k   (spline: 0..48, base: 49..55)
#define NT2  25            // n8 tiles layer2 (200 = 196 padded to 8)
#define NC2  108           // (spline: 0..95, base: 96..107)

#define MTILE 64
#define NTH  256
#define L2E  1.4426950408889634f

#define W1ELEMS (112u * 48u * 64u)     // 344064 uints
#define W2ELEMS (216u * 25u * 64u)     // 345600 uints
#define L2CHUNK (25u * 64u * 2u)       // 3200 uints per 32-k chunk

__device__ unsigned g_W1[W1ELEMS];   // 1.31 MB
__device__ unsigned g_W2[W2ELEMS];   // 1.32 MB

// ----------------------------- helpers --------------------------------------
static __device__ __forceinline__ float ex2f(float z) {
    float r; asm("ex2.approx.ftz.f32 %0, %1;" : "=f"(r) : "f"(z)); return r;
}
static __device__ __forceinline__ float rcpf(float z) {
    float r; asm("rcp.approx.ftz.f32 %0, %1;" : "=f"(r) : "f"(z)); return r;
}
static __device__ __forceinline__ float basis_feat(float v, int q) {
    float u = (v + 1.0f) * 3.5f - (float)q;
    float z = fmaxf(-u * u * L2E, -126.0f);
    return ex2f(z);
}
static __device__ __forceinline__ float silu_feat(float v) {
    float z = fminf(fmaxf(-v * L2E, -126.0f), 126.0f);
    return v * rcpf(1.0f + ex2f(z));
}
static __device__ __forceinline__ unsigned h2pack(float a, float b) {
    __half2 h = __floats2half2_rn(a, b);
    return *reinterpret_cast<unsigned*>(&h);
}
// fp32-accumulator MMA
static __device__ __forceinline__ void mma16(float* d, const uint4& A, const uint2& B) {
    asm volatile(
        "mma.sync.aligned.m16n8k16.row.col.f32.f16.f16.f32 "
        "{%0,%1,%2,%3}, {%4,%5,%6,%7}, {%8,%9}, {%0,%1,%2,%3};"
        : "+f"(d[0]), "+f"(d[1]), "+f"(d[2]), "+f"(d[3])
        : "r"(A.x), "r"(A.y), "r"(A.z), "r"(A.w), "r"(B.x), "r"(B.y));
}
// fp16-accumulator MMA (rate experiment)
static __device__ __forceinline__ void mma16h(unsigned* d, const uint4& A, const uint2& B) {
    asm volatile(
        "mma.sync.aligned.m16n8k16.row.col.f16.f16.f16.f16 "
        "{%0,%1}, {%2,%3,%4,%5}, {%6,%7}, {%0,%1};"
        : "+r"(d[0]), "+r"(d[1])
        : "r"(A.x), "r"(A.y), "r"(A.z), "r"(A.w), "r"(B.x), "r"(B.y));
}
static __device__ __forceinline__ void cpasync16(void* dst, const void* src) {
    unsigned s = (unsigned)__cvta_generic_to_shared(dst);
    asm volatile("cp.async.cg.shared.global [%0], [%1], 16;" :: "r"(s), "l"(src));
}
static __device__ __forceinline__ void cp_commit() {
    asm volatile("cp.async.commit_group;" ::: "memory");
}
static __device__ __forceinline__ void cp_wait0() {
    asm volatile("cp.async.wait_group 0;" ::: "memory");
}

// ------------------------- fused weight prep --------------------------------
__global__ void prep(const float* __restrict__ sw1, const float* __restrict__ bw1,
                     const float* __restrict__ sw2, const float* __restrict__ bw2) {
    unsigned gi = blockIdx.x * blockDim.x + threadIdx.x;
    if (gi < W1ELEMS) {
        unsigned idx = gi;
        unsigned r = idx & 1, lane = (idx >> 1) & 31;
        unsigned nt = (idx >> 6) % 48, ks = (idx >> 6) / 48;
        unsigned n = nt * 8 + (lane >> 2);
        unsigned k = ks * 16 + r * 8 + (lane & 3) * 2;
        float v0 = 0.0f, v1 = 0.0f;
        if (k < 1568)       v0 = sw1[n * 1568 + k];
        else if (k < 1764)  v0 = bw1[n * 196 + (k - 1568)];
        unsigned k1 = k + 1;
        if (k1 < 1568)      v1 = sw1[n * 1568 + k1];
        else if (k1 < 1764) v1 = bw1[n * 196 + (k1 - 1568)];
        g_W1[idx] = h2pack(v0, v1);
    } else if (gi < W1ELEMS + W2ELEMS) {
        unsigned idx = gi - W1ELEMS;
        unsigned r = idx & 1, lane = (idx >> 1) & 31;
        unsigned nt = (idx >> 6) % 25, ks = (idx >> 6) / 25;
        unsigned n = nt * 8 + (lane >> 2);
        unsigned k = ks * 16 + r * 8 + (lane & 3) * 2;
        float v0 = 0.0f, v1 = 0.0f;
        if (n < PP) {
            if (k < 3072)       v0 = sw2[n * 3072 + k];
            else                v0 = bw2[n * 384 + (k - 3072)];
            unsigned k1 = k + 1;
            if (k1 < 3072)      v1 = sw2[n * 3072 + k1];
            else                v1 = bw2[n * 384 + (k1 - 3072)];
        }
        g_W2[idx] = h2pack(v0, v1);
    }
}

// ------------------------------ main kernel ---------------------------------
// smem (float units): same as the 530.9us baseline
#define SM_B1   0
#define SM_B2   384
#define SM_R0   640
#define SM_A0   13184
#define SM_A1   14208
#define SM_BS0  15232
#define SM_BS1  21376
#define SM_TOTF 27520
#define HST     392        // h stride in halfs

__global__ void __launch_bounds__(NTH, 2)
kan_main(const float* __restrict__ x, const float* __restrict__ b1,
         const float* __restrict__ b2, float* __restrict__ out) {
    extern __shared__ float smem[];
    float*  b1s = smem + SM_B1;
    float*  b2s = smem + SM_B2;
    float*  xs  = smem + SM_R0;                              // fp32 [196][64]
    __half* hs  = reinterpret_cast<__half*>(smem + SM_R0);   // fp16 [64][392]
    unsigned* Bsu[2] = { reinterpret_cast<unsigned*>(smem + SM_BS0),
                         reinterpret_cast<unsigned*>(smem + SM_BS1) };
    uint4* As4[2] = { reinterpret_cast<uint4*>(smem + SM_A0),
                      reinterpret_cast<uint4*>(smem + SM_A1) };

    const int tid = threadIdx.x;
    const int w = tid >> 5, lane = tid & 31;
    const int mw = w & 1;           // row half
    const int nG = w >> 1;          // col group 0..3
    const int g = lane >> 2, c4 = lane & 3;
    const int nt2_base = (nG == 0) ? 0 : (1 + 6 * nG);   // 0,7,13,19
    const int nt2_cnt  = (nG == 0) ? 7 : 6;
    // feature-gen decomposition (per-thread fragment word)
    const int fmt = tid >> 6, fks = (tid >> 5) & 1;
    const int fc4 = c4;
    const int fr0 = fmt * 16 + g, fr1 = fr0 + 8;

    const int m0 = blockIdx.x * MTILE;
    const int b  = m0 / CC;
    const int c0 = m0 % CC;

    // per-chunk A-fragment generators (one uint4 per thread)
    auto genA1 = [&](int kc, uint4* dst) {
        const int k0 = kc * 32;
        const int kb0 = k0 + fks * 16 + fc4 * 2;
        const int kb1 = kb0 + 8;
        uint4 aw;
        if (kc < 49) {
            const int p0 = kb0 >> 3, q0 = kb0 & 7;
            const int p1 = kb1 >> 3, q1 = kb1 & 7;
            float x00 = xs[p0 * 64 + fr0], x01 = xs[p0 * 64 + fr1];
            float x10 = xs[p1 * 64 + fr0], x11 = xs[p1 * 64 + fr1];
            aw.x = h2pack(basis_feat(x00, q0), basis_feat(x00, q0 + 1));
            aw.y = h2pack(basis_feat(x01, q0), basis_feat(x01, q0 + 1));
            aw.z = h2pack(basis_feat(x10, q1), basis_feat(x10, q1 + 1));
            aw.w = h2pack(basis_feat(x11, q1), basis_feat(x11, q1 + 1));
        } else {
            float f00 = (kb0 < 1764) ? silu_feat(xs[(kb0 - 1568) * 64 + fr0]) : 0.0f;
            float f01 = (kb0 + 1 < 1764) ? silu_feat(xs[(kb0 - 1567) * 64 + fr0]) : 0.0f;
            float f02 = (kb0 < 1764) ? silu_feat(xs[(kb0 - 1568) * 64 + fr1]) : 0.0f;
            float f03 = (kb0 + 1 < 1764) ? silu_feat(xs[(kb0 - 1567) * 64 + fr1]) : 0.0f;
            float f10 = (kb1 < 1764) ? silu_feat(xs[(kb1 - 1568) * 64 + fr0]) : 0.0f;
            float f11 = (kb1 + 1 < 1764) ? silu_feat(xs[(kb1 - 1567) * 64 + fr0]) : 0.0f;
            float f12 = (kb1 < 1764) ? silu_feat(xs[(kb1 - 1568) * 64 + fr1]) : 0.0f;
            float f13 = (kb1 + 1 < 1764) ? silu_feat(xs[(kb1 - 1567) * 64 + fr1]) : 0.0f;
            aw.x = h2pack(f00, f01);
            aw.y = h2pack(f02, f03);
            aw.z = h2pack(f10, f11);
            aw.w = h2pack(f12, f13);
        }
        dst[tid] = aw;
    };

    auto genA2 = [&](int kc, uint4* dst) {
        const int k0 = kc * 32;
        const int kb0 = k0 + fks * 16 + fc4 * 2;
        const int kb1 = kb0 + 8;
        uint4 aw;
        if (kc < 96) {
            const int j0 = kb0 >> 3, q0 = kb0 & 7;
            const int j1 = kb1 >> 3, q1 = kb1 & 7;
            float h00 = __half2float(hs[fr0 * HST + j0]);
            float h01 = __half2float(hs[fr1 * HST + j0]);
            float h10 = __half2float(hs[fr0 * HST + j1]);
            float h11 = __half2float(hs[fr1 * HST + j1]);
            aw.x = h2pack(basis_feat(h00, q0), basis_feat(h00, q0 + 1));
            aw.y = h2pack(basis_feat(h01, q0), basis_feat(h01, q0 + 1));
            aw.z = h2pack(basis_feat(h10, q1), basis_feat(h10, q1 + 1));
            aw.w = h2pack(basis_feat(h11, q1), basis_feat(h11, q1 + 1));
        } else {
            const int j00 = kb0 - 3072, j10 = kb1 - 3072;
            float f00 = silu_feat(__half2float(hs[fr0 * HST + j00]));
            float f01 = silu_feat(__half2float(hs[fr0 * HST + j00 + 1]));
            float f02 = silu_feat(__half2float(hs[fr1 * HST + j00]));
            float f03 = silu_feat(__half2float(hs[fr1 * HST + j00 + 1]));
            float f10 = silu_feat(__half2float(hs[fr0 * HST + j10]));
            float f11 = silu_feat(__half2float(hs[fr0 * HST + j10 + 1]));
            float f12 = silu_feat(__half2float(hs[fr1 * HST + j10]));
            float f13 = silu_feat(__half2float(hs[fr1 * HST + j10 + 1]));
            aw.x = h2pack(f00, f01);
            aw.y = h2pack(f02, f03);
            aw.z = h2pack(f10, f11);
            aw.w = h2pack(f12, f13);
        }
        dst[tid] = aw;
    };

    // weight prefetch helpers
    auto prefW1 = [&](int kc, int bi) {   // stage W1 chunk kc into Bs[bi]
        const unsigned* src = g_W1 + (size_t)kc * 6144;
        unsigned* dst = Bsu[bi];
#pragma unroll
        for (int i = 0; i < 6; ++i) {
            int v = tid + i * NTH;
            cpasync16(dst + v * 4, src + (size_t)v * 4);
        }
        cp_commit();
    };
    auto prefW2 = [&](int kc, int bi) {   // stage W2 chunk kc into Bs[bi]
        const unsigned* src = g_W2 + (size_t)kc * L2CHUNK;
        unsigned* dst = Bsu[bi];
#pragma unroll
        for (int i = 0; i < 3; ++i) {
            int v = tid + i * NTH;
            cpasync16(dst + v * 4, src + (size_t)v * 4);
        }
        if (tid < 32) cpasync16(dst + (768 + tid) * 4, src + (size_t)(768 + tid) * 4);
        cp_commit();
    };

    // ---- prefetch L1 chunk 0 weights ----
    prefW1(0, 0);

    // ---- load x slab + biases ----
    {
        const float4* xg = reinterpret_cast<const float4*>(x + (size_t)b * PP * CC + c0);
        float4* xs4 = reinterpret_cast<float4*>(xs);
        for (int i = tid; i < PP * 16; i += NTH) {
            int p = i >> 4, r4 = i & 15;
            xs4[p * 16 + r4] = xg[p * (CC / 4) + r4];
        }
        for (int i = tid; i < HSZ; i += NTH) b1s[i] = b1[i];
        if (tid < 200) b2s[tid] = (tid < PP) ? b2[tid] : 0.0f;
    }
    __syncthreads();

    // ============================ layer 1 ============================
    {
        float acc[2][12][4];

        // ---- spline region: fp16 accumulators ----
        {
            unsigned hacc[2][12][2] = {};
            genA1(0, As4[0]);
            for (int kc = 0; kc < 49; ++kc) {
                const int bi = kc & 1;
                cp_wait0();
                __syncthreads();
                prefW1(kc + 1, bi ^ 1);              // kc+1 <= 49 < NC1, valid
                genA1(kc + 1, As4[bi ^ 1]);
                const uint2* Bs2 = reinterpret_cast<const uint2*>(Bsu[bi]);
#pragma unroll
                for (int ks = 0; ks < 2; ++ks) {
                    uint4 Af[2];
#pragma unroll
                    for (int mi = 0; mi < 2; ++mi)
                        Af[mi] = As4[bi][((mw * 2 + mi) * 2 + ks) * 32 + lane];
#pragma unroll
                    for (int nti = 0; nti < 12; ++nti) {
                        int nt = nG * 12 + nti;
                        uint2 Bf = Bs2[(ks * NT1 + nt) * 32 + lane];
#pragma unroll
                        for (int mi = 0; mi < 2; ++mi) mma16h(hacc[mi][nti], Af[mi], Bf);
                    }
                }
            }
            // streamed merge f16 -> f32 (per-tile so hacc regs die progressively)
#pragma unroll
            for (int mi = 0; mi < 2; ++mi)
#pragma unroll
                for (int nti = 0; nti < 12; ++nti) {
                    float2 lo = __half22float2(*reinterpret_cast<__half2*>(&hacc[mi][nti][0]));
                    float2 hi = __half22float2(*reinterpret_cast<__half2*>(&hacc[mi][nti][1]));
                    acc[mi][nti][0] = lo.x; acc[mi][nti][1] = lo.y;
                    acc[mi][nti][2] = hi.x; acc[mi][nti][3] = hi.y;
                }
        }

        // ---- base region: fp32 accumulators ----
        for (int kc = 49; kc < NC1; ++kc) {
            const int bi = kc & 1;
            cp_wait0();
            __syncthreads();
            if (kc + 1 < NC1) {
                prefW1(kc + 1, bi ^ 1);
                genA1(kc + 1, As4[bi ^ 1]);
            } else {
                prefW2(0, 0);                        // last L1 chunk (odd) -> W2(0) into Bs0
            }
            const uint2* Bs2 = reinterpret_cast<const uint2*>(Bsu[bi]);
#pragma unroll
            for (int ks = 0; ks < 2; ++ks) {
                uint4 Af[2];
#pragma unroll
                for (int mi = 0; mi < 2; ++mi)
                    Af[mi] = As4[bi][((mw * 2 + mi) * 2 + ks) * 32 + lane];
#pragma unroll
                for (int nti = 0; nti < 12; ++nti) {
                    int nt = nG * 12 + nti;
                    uint2 Bf = Bs2[(ks * NT1 + nt) * 32 + lane];
#pragma unroll
                    for (int mi = 0; mi < 2; ++mi) mma16(acc[mi][nti], Af[mi], Bf);
                }
            }
        }

        __syncthreads();   // all xs reads done before hs overwrite

        // ---- h epilogue: hs[row][col] = fp16(acc + b1[col]) ----
#pragma unroll
        for (int mi = 0; mi < 2; ++mi)
#pragma unroll
            for (int nti = 0; nti < 12; ++nti)
#pragma unroll
                for (int ci = 0; ci < 4; ++ci) {
                    int row = mw * 32 + mi * 16 + g + 8 * (ci >> 1);
                    int col = nG * 96 + nti * 8 + 2 * c4 + (ci & 1);
                    hs[row * HST + col] = __float2half(acc[mi][nti][ci] + b1s[col]);
                }
    }
    __syncthreads();       // hs visible to all

    // ============================ layer 2 ============================
    {
        float acc[2][7][4];

        // ---- spline region: fp16 accumulators ----
        {
            unsigned hacc[2][7][2] = {};
            genA2(0, As4[0]);
            for (int kc = 0; kc < 96; ++kc) {
                const int bi = kc & 1;
                cp_wait0();
                __syncthreads();
                prefW2(kc + 1, bi ^ 1);              // kc+1 <= 96 < NC2, valid
                genA2(kc + 1, As4[bi ^ 1]);
                const uint2* Bs2 = reinterpret_cast<const uint2*>(Bsu[bi]);
#pragma unroll
                for (int ks = 0; ks < 2; ++ks) {
                    uint4 Af[2];
#pragma unroll
                    for (int mi = 0; mi < 2; ++mi)
                        Af[mi] = As4[bi][((mw * 2 + mi) * 2 + ks) * 32 + lane];
#pragma unroll
                    for (int nti = 0; nti < 7; ++nti) {
                        if (nti < nt2_cnt) {
                            int nt = nt2_base + nti;
                            uint2 Bf = Bs2[(ks * NT2 + nt) * 32 + lane];
#pragma unroll
                            for (int mi = 0; mi < 2; ++mi) mma16h(hacc[mi][nti], Af[mi], Bf);
                        }
                    }
                }
            }
#pragma unroll
            for (int mi = 0; mi < 2; ++mi)
#pragma unroll
                for (int nti = 0; nti < 7; ++nti) {
                    float2 lo = __half22float2(*reinterpret_cast<__half2*>(&hacc[mi][nti][0]));
                    float2 hi = __half22float2(*reinterpret_cast<__half2*>(&hacc[mi][nti][1]));
                    acc[mi][nti][0] = lo.x; acc[mi][nti][1] = lo.y;
                    acc[mi][nti][2] = hi.x; acc[mi][nti][3] = hi.y;
                }
        }

        // ---- base region: fp32 accumulators ----
        for (int kc = 96; kc < NC2; ++kc) {
            const int bi = kc & 1;
            cp_wait0();
            __syncthreads();
            if (kc + 1 < NC2) {
                prefW2(kc + 1, bi ^ 1);
                genA2(kc + 1, As4[bi ^ 1]);
            }
            const uint2* Bs2 = reinterpret_cast<const uint2*>(Bsu[bi]);
#pragma unroll
            for (int ks = 0; ks < 2; ++ks) {
                uint4 Af[2];
#pragma unroll
                for (int mi = 0; mi < 2; ++mi)
                    Af[mi] = As4[bi][((mw * 2 + mi) * 2 + ks) * 32 + lane];
#pragma unroll
                for (int nti = 0; nti < 7; ++nti) {
                    if (nti < nt2_cnt) {
                        int nt = nt2_base + nti;
                        uint2 Bf = Bs2[(ks * NT2 + nt) * 32 + lane];
#pragma unroll
                        for (int mi = 0; mi < 2; ++mi) mma16(acc[mi][nti], Af[mi], Bf);
                    }
                }
            }
        }

        // ---- epilogue: out = acc + b2[p] + x ----
#pragma unroll
        for (int mi = 0; mi < 2; ++mi)
#pragma unroll
            for (int nti = 0; nti < 7; ++nti) {
                if (nti < nt2_cnt) {
#pragma unroll
                    for (int ci = 0; ci < 4; ++ci) {
                        int row = mw * 32 + mi * 16 + g + 8 * (ci >> 1);
                        int p   = (nt2_base + nti) * 8 + 2 * c4 + (ci & 1);
                        if (p < PP) {
                            size_t ga = ((size_t)b * PP + p) * CC + c0 + row;
                            out[ga] = acc[mi][nti][ci] + b2s[p] + x[ga];
                        }
                    }
                }
            }
    }
}

// ------------------------------ launcher ------------------------------------
extern "C" void kernel_launch(void* const* d_in, const int* in_sizes, int n_in,
                              void* d_out, int out_size) {
    (void)in_sizes; (void)n_in; (void)out_size;
    const float* x  = (const float*)d_in[0];
    const float* s1 = (const float*)d_in[1];
    const float* w1 = (const float*)d_in[2];
    const float* b1 = (const float*)d_in[3];
    const float* s2 = (const float*)d_in[4];
    const float* w2 = (const float*)d_in[5];
    const float* b2 = (const float*)d_in[6];
    float* out = (float*)d_out;

    prep<<<(W1ELEMS + W2ELEMS + 255) / 256, 256>>>(s1, w1, s2, w2);

    const int smemBytes = SM_TOTF * 4;   // 110,080 B -> 2 CTAs/SM
    cudaFuncSetAttribute(kan_main, cudaFuncAttributeMaxDynamicSharedMemorySize, smemBytes);
    kan_main<<<(64 * CC) / MTILE, NTH, smemBytes>>>(x, b1, b2, out);
}